// round 13
// baseline (speedup 1.0000x reference)
#include <cuda_runtime.h>
#include <math.h>

// ---------------- problem constants ----------------
#define BATCH   32
#define NBANDS  80
#define NFR     2000
#define LLEN    320000
#define NFFT    512
#define HOP     128
#define PADW    256
#define NFREQ   257           // rfft bins
#define TFRAMES 2501          // LLEN/HOP + 1
#define NPAIR   1251          // ceil(TFRAMES/2)
#define NPAIR2  626           // ceil(NPAIR/2): two pairs per block

// ---------------- device globals (scratch; no allocation allowed) ----------------
__device__ int           g_band[NFREQ];
__device__ float2        g_tw[NFFT];          // cis(-pi*j/256) = W512^j
__device__ float         g_win[NFFT];
__device__ float         g_yf[(size_t)BATCH * TFRAMES * NFFT];   // windowed ISTFT frames (~164 MB)
__device__ unsigned int  g_maxbits[BATCH];

// ---------------- complex helpers ----------------
__device__ __forceinline__ float2 cadd(float2 a, float2 b){ return make_float2(a.x+b.x, a.y+b.y); }
__device__ __forceinline__ float2 csub(float2 a, float2 b){ return make_float2(a.x-b.x, a.y-b.y); }
__device__ __forceinline__ float2 cmul(float2 a, float2 b){ return make_float2(a.x*b.x - a.y*b.y, a.x*b.y + a.y*b.x); }
__device__ __forceinline__ float2 cmulc(float2 a, float2 b){ // a * conj(b)
    return make_float2(a.x*b.x + a.y*b.y, a.y*b.x - a.x*b.y);
}

// Conflict-free smem address for logical digits (h,m,l) in 8x8x8.
__device__ __forceinline__ int swz(int h, int m, int l) {
    return (h << 6) | (((m ^ h) & 7) << 3) | ((l ^ m) & 7);
}

// 8-point DFT, in place, natural order in/out.
// S = -1: forward; S = +1: inverse kernel, unnormalized.
template<int S>
__device__ __forceinline__ void fft8(float2* x) {
    float2 t0 = cadd(x[0], x[4]), t4 = csub(x[0], x[4]);
    float2 t1 = cadd(x[1], x[5]), t5 = csub(x[1], x[5]);
    float2 t2 = cadd(x[2], x[6]), t6 = csub(x[2], x[6]);
    float2 t3 = cadd(x[3], x[7]), t7 = csub(x[3], x[7]);
    const float rh = 0.70710678118654752440f;
    #define MULJ(z) ((S < 0) ? make_float2((z).y, -(z).x) : make_float2(-(z).y, (z).x))
    float2 o1 = (S < 0) ? make_float2((t5.x + t5.y)*rh, (t5.y - t5.x)*rh)
                        : make_float2((t5.x - t5.y)*rh, (t5.x + t5.y)*rh);
    float2 o2 = MULJ(t6);
    float2 o3 = (S < 0) ? make_float2((t7.y - t7.x)*rh, -(t7.x + t7.y)*rh)
                        : make_float2(-(t7.x + t7.y)*rh, (t7.x - t7.y)*rh);
    float2 u0 = cadd(t0, t2), u2 = csub(t0, t2);
    float2 u1 = cadd(t1, t3), u3 = csub(t1, t3);
    x[0] = cadd(u0, u1); x[4] = csub(u0, u1);
    float2 ju3 = MULJ(u3);
    x[2] = cadd(u2, ju3); x[6] = csub(u2, ju3);
    float2 p0 = cadd(t4, o2), p2 = csub(t4, o2);
    float2 p1 = cadd(o1, o3), p3 = csub(o1, o3);
    x[1] = cadd(p0, p1); x[5] = csub(p0, p1);
    float2 jp3 = MULJ(p3);
    x[3] = cadd(p2, jp3); x[7] = csub(p2, jp3);
    #undef MULJ
}

// ---------------- setup: band table, twiddles, window, max reset ----------------
__global__ void setup_kernel() {
    __shared__ float edges[NBANDS + 1];
    int t = threadIdx.x;
    if (t <= NBANDS) {
        double mel_max = 2595.0 * log10(1.0 + 8000.0 / 700.0);
        double mel = mel_max * (double)t / (double)NBANDS;
        double hz = 700.0 * (pow(10.0, mel / 2595.0) - 1.0);
        edges[t] = (float)(hz / 8000.0);
    }
    if (t < NFFT) {
        double ang = -M_PI * (double)t / 256.0;
        g_tw[t] = make_float2((float)cos(ang), (float)sin(ang));
        double w = 0.5 * (1.0 - cos(2.0 * M_PI * (double)t / (double)NFFT));
        g_win[t] = (float)w;
    }
    if (t < BATCH) g_maxbits[t] = 0u;
    __syncthreads();
    if (t < NFREQ) {
        float fr = (float)t / 256.0f;
        int cnt = 0;
        #pragma unroll 1
        for (int i = 0; i <= NBANDS; i++) cnt += (edges[i] <= fr) ? 1 : 0;
        int bd = cnt - 1;
        if (bd < 0 || bd >= NBANDS) bd = -1;
        g_band[t] = bd;
    }
}

// ---------------- fused STFT-filter-ISTFT ----------------
// 128 threads/block = two independent 64-thread FFT groups, each handling one
// frame-pair (two real frames packed re/im into one complex 512-pt FFT).
__global__ void __launch_bounds__(128) fft_filter_kernel(const float* __restrict__ mags,
                                                         const float* __restrict__ noise) {
    int b    = blockIdx.y;
    int grp  = threadIdx.x >> 6;                 // 0 or 1: which FFT group
    int pair = blockIdx.x * 2 + grp;
    bool live = (pair < NPAIR);
    if (!live) pair = NPAIR - 1;                 // keep group in lockstep; writes masked
    int tA = 2 * pair, tB = tA + 1;
    bool hasB = (tB < TFRAMES);
    int t = threadIdx.x & 63;                    // 0..63 within group
    int u = t >> 3, v = t & 7;

    __shared__ float2 exs[2][NFFT];
    __shared__ float  c1ss[2][NFREQ], c2ss[2][NFREQ];
    float2* ex = exs[grp];
    float* c1s = c1ss[grp];
    float* c2s = c2ss[grp];

    // ---- exact interpolation coordinates: pos = tA * (NFR-1) / (TFRAMES-1) ----
    int numA = tA * (NFR - 1);
    int iA0 = numA / (TFRAMES - 1);
    float wA = (float)(numA - iA0 * (TFRAMES - 1)) * (1.0f / (float)(TFRAMES - 1));
    int iA1 = min(iA0 + 1, NFR - 1);
    int numB = tB * (NFR - 1);
    int iB0 = numB / (TFRAMES - 1);
    float wB = (float)(numB - iB0 * (TFRAMES - 1)) * (1.0f / (float)(TFRAMES - 1));
    int iB1 = min(iB0 + 1, NFR - 1);

    // ---- per-frame band magnitudes -> per-bin combine coefficients ----
    for (int f = t; f < NFREQ; f += 64) {
        int bd = g_band[f];
        float m1 = 0.f, m2 = 0.f;
        if (bd >= 0) {
            const float* mrow = mags + ((size_t)b * NBANDS + bd) * NFR;
            m1 = mrow[iA0] * (1.f - wA) + mrow[iA1] * wA;
            if (hasB) m2 = mrow[iB0] * (1.f - wB) + mrow[iB1] * wB;
        }
        c1s[f] = 0.5f * (m1 + m2);
        c2s[f] = 0.5f * (m1 - m2);
    }

    // ---- load two windowed frames packed as complex (re=A, im=B) ----
    float2 r[8];
    float  winr[8];
    int baseA = tA * HOP;
    const float* nrow = noise + (size_t)b * LLEN;
    #pragma unroll
    for (int c = 0; c < 8; c++) {
        int n = 64 * c + t;
        float wv = g_win[n];
        winr[c] = wv;
        int p = baseA + n;
        int j = p - PADW; j = (j < 0) ? -j : j; j = (j >= LLEN) ? (2 * (LLEN - 1) - j) : j;
        float xa = nrow[j] * wv;
        float xb = 0.f;
        if (hasB) {
            int p2 = p + HOP;
            int j2 = p2 - PADW; j2 = (j2 < 0) ? -j2 : j2; j2 = (j2 >= LLEN) ? (2 * (LLEN - 1) - j2) : j2;
            xb = nrow[j2] * wv;
        }
        r[c] = make_float2(xa, xb);
    }

    // ---- forward 512-pt FFT: radix-8 x3; n = 64c + 8u + v ----
    fft8<-1>(r);
    #pragma unroll
    for (int g = 1; g < 8; g++) r[g] = cmul(r[g], g_tw[g * t]);           // W512^(g*t)
    #pragma unroll
    for (int g = 0; g < 8; g++) ex[swz(g, u, v)] = r[g];
    __syncthreads();
    #pragma unroll
    for (int bb = 0; bb < 8; bb++) r[bb] = ex[swz(u, bb, v)];
    fft8<-1>(r);
    #pragma unroll
    for (int g = 1; g < 8; g++) r[g] = cmul(r[g], g_tw[8 * g * v]);       // W64^(g*v)
    __syncthreads();
    #pragma unroll
    for (int g = 0; g < 8; g++) ex[swz(u, g, v)] = r[g];
    __syncthreads();
    #pragma unroll
    for (int a = 0; a < 8; a++) r[a] = ex[swz(u, v, a)];
    fft8<-1>(r);
    __syncthreads();
    #pragma unroll
    for (int al = 0; al < 8; al++) ex[swz(al, v, u)] = r[al];             // k = 64*al + 8*v + u
    __syncthreads();

    // ---- mask: Z'[k] = c1*Z[k] + c2*conj(Z[512-k]) ----
    #pragma unroll
    for (int al = 0; al < 8; al++) {
        int k  = al * 64 + t;
        int kn = (NFFT - k) & (NFFT - 1);
        int kh = min(k, NFFT - k);
        float2 z1 = ex[swz(al, u, v)];
        float2 z2 = ex[swz(kn >> 6, (kn >> 3) & 7, kn & 7)];
        float c1 = c1s[kh], c2 = c2s[kh];
        r[al] = make_float2(c1 * z1.x + c2 * z2.x, c1 * z1.y - c2 * z2.y);
    }

    // ---- inverse 512-pt FFT (conjugate twiddles), same structure ----
    fft8<1>(r);
    #pragma unroll
    for (int g = 1; g < 8; g++) r[g] = cmulc(r[g], g_tw[g * t]);
    __syncthreads();
    #pragma unroll
    for (int g = 0; g < 8; g++) ex[swz(g, u, v)] = r[g];
    __syncthreads();
    #pragma unroll
    for (int bb = 0; bb < 8; bb++) r[bb] = ex[swz(u, bb, v)];
    fft8<1>(r);
    #pragma unroll
    for (int g = 1; g < 8; g++) r[g] = cmulc(r[g], g_tw[8 * g * v]);
    __syncthreads();
    #pragma unroll
    for (int g = 0; g < 8; g++) ex[swz(u, g, v)] = r[g];
    __syncthreads();
    #pragma unroll
    for (int a = 0; a < 8; a++) r[a] = ex[swz(u, v, a)];
    fft8<1>(r);
    __syncthreads();
    #pragma unroll
    for (int al = 0; al < 8; al++) ex[swz(al, v, u)] = r[al];             // natural n order
    __syncthreads();

    // ---- write windowed ISTFT frames (coalesced; OLA done by gather) ----
    if (live) {
        float* fA = g_yf + ((size_t)b * TFRAMES + tA) * NFFT;
        const float inv = 1.0f / (float)NFFT;
        #pragma unroll
        for (int c = 0; c < 8; c++) {
            int n = 64 * c + t;
            float2 yv = ex[swz(c, u, v)];
            float s = winr[c] * inv;
            fA[n] = yv.x * s;
            if (hasB) fA[NFFT + n] = yv.y * s;    // frame tB = tA+1, contiguous row
        }
    }
}

// ---------------- OLA gather + window-square normalization + per-batch abs-max ----------------
__global__ void norm1_kernel(float* __restrict__ out) {
    int b  = blockIdx.y;
    int i0 = (blockIdx.x * blockDim.x + threadIdx.x) * 4;
    float vmax = 0.f;
    if (i0 < LLEN) {
        int p = i0 + PADW;                      // padded coordinate; multiple of 4
        int tlo = (p - 384) >> 7; if (tlo < 0) tlo = 0;
        int thi = p >> 7;         if (thi > TFRAMES - 1) thi = TFRAMES - 1;
        const float* base = g_yf + (size_t)b * TFRAMES * NFFT;
        float4 acc = make_float4(0.f, 0.f, 0.f, 0.f);
        for (int tt = tlo; tt <= thi; tt++) {
            float4 yv = *reinterpret_cast<const float4*>(base + (size_t)tt * NFFT + (p - HOP * tt));
            acc.x += yv.x; acc.y += yv.y; acc.z += yv.z; acc.w += yv.w;
        }
        float res[4] = { acc.x, acc.y, acc.z, acc.w };
        if (thi - tlo == 3) {
            const float di = 1.0f / 1.5f;       // interior: periodic-hann^2 4x-overlap sum = 1.5
            #pragma unroll
            for (int j = 0; j < 4; j++) res[j] *= di;
        } else {
            #pragma unroll
            for (int j = 0; j < 4; j++) {
                int pj = p + j;
                float d = 0.f;
                for (int tt = tlo; tt <= thi; tt++) {
                    float wv = g_win[pj - HOP * tt];
                    d += wv * wv;
                }
                if (d <= 1e-11f) d = 1.f;
                res[j] /= d;
            }
        }
        #pragma unroll
        for (int j = 0; j < 4; j++) vmax = fmaxf(vmax, fabsf(res[j]));
        *reinterpret_cast<float4*>(out + (size_t)b * LLEN + i0) =
            make_float4(res[0], res[1], res[2], res[3]);
    }
    #pragma unroll
    for (int o = 16; o; o >>= 1) vmax = fmaxf(vmax, __shfl_xor_sync(0xffffffffu, vmax, o));
    if ((threadIdx.x & 31) == 0) atomicMax(&g_maxbits[b], __float_as_uint(vmax));
}

__global__ void norm2_kernel(float* __restrict__ out) {
    int b  = blockIdx.y;
    int i0 = (blockIdx.x * blockDim.x + threadIdx.x) * 4;
    if (i0 >= LLEN) return;
    float mx = __uint_as_float(g_maxbits[b]);
    float s = 1.0f / (mx + 1e-8f);
    float4* p = reinterpret_cast<float4*>(out + (size_t)b * LLEN + i0);
    float4 vv = *p;
    vv.x *= s; vv.y *= s; vv.z *= s; vv.w *= s;
    *p = vv;
}

// ---------------- launcher ----------------
extern "C" void kernel_launch(void* const* d_in, const int* in_sizes, int n_in,
                              void* d_out, int out_size) {
    const float* mags  = (const float*)d_in[0];
    const float* noise = (const float*)d_in[1];
    float* out = (float*)d_out;

    setup_kernel<<<1, 512>>>();

    dim3 gfft(NPAIR2, BATCH);
    fft_filter_kernel<<<gfft, 128>>>(mags, noise);

    dim3 gnorm((LLEN / 4 + 255) / 256, BATCH);
    norm1_kernel<<<gnorm, 256>>>(out);
    norm2_kernel<<<gnorm, 256>>>(out);
}